// round 3
// baseline (speedup 1.0000x reference)
#include <cuda_runtime.h>
#include <cuda_bf16.h>

// Problem constants (fixed by the reference setup_inputs)
#define BB 2
#define NN 8192
#define MM 32768
#define SS 4096

#define TPB 128          // threads per block (main kernel)
#define PPT 8            // points per thread
#define PPB (TPB * PPT)  // 1024 points per block
#define SBLOCKS ((BB * SS) / PPB)  // 8
#define MCHUNKS 37
#define CHUNK 896        // 37 * 896 = 33152 >= 32768 (last chunk bounds-checked)

// Device scratch (no allocations allowed)
__device__ float4 g_target4[BB * MM];   // (tx, ty, tz, |t|^2)
__device__ float4 g_pred4[BB * SS];     // (-2px, -2py, -2pz, |p|^2)
__device__ int    g_minbuf[BB * SS];    // min d^2 as int bits (nonneg floats order as ints)

__global__ void prep_target_kernel(const float* __restrict__ target) {
    int i = blockIdx.x * blockDim.x + threadIdx.x;
    if (i < BB * MM) {
        float x = target[3 * i + 0];
        float y = target[3 * i + 1];
        float z = target[3 * i + 2];
        g_target4[i] = make_float4(x, y, z, x * x + y * y + z * z);
    }
}

// idx is int32 on device: JAX with default x64-disabled config coerces
// jnp.int64 -> int32, so the harness buffer holds 4096 int32 values.
__global__ void prep_pred_kernel(const float* __restrict__ pred,
                                 const int* __restrict__ idx) {
    int i = blockIdx.x * blockDim.x + threadIdx.x;  // over B*S
    if (i < BB * SS) {
        int b = i / SS;
        int s = i % SS;
        int j = idx[s];
        j = min(max(j, 0), NN - 1);  // defensive clamp (no-op for valid input)
        const float* p = pred + ((long long)b * NN + j) * 3;
        float x = p[0], y = p[1], z = p[2];
        g_pred4[i] = make_float4(-2.0f * x, -2.0f * y, -2.0f * z,
                                 x * x + y * y + z * z);
        g_minbuf[i] = 0x7F800000;  // +inf
    }
}

__global__ void __launch_bounds__(TPB) chamfer_main_kernel() {
    __shared__ float4 tile[CHUNK];

    const int sblk = blockIdx.x;            // 0..SBLOCKS-1
    const int mblk = blockIdx.y;            // 0..MCHUNKS-1
    const int pbase = sblk * PPB;           // global point base in [0, B*S)
    const int b = pbase / SS;               // batch of this point block
    const int mbase = mblk * CHUNK;
    const int mcount = min(CHUNK, MM - mbase);

    // Load target chunk into shared memory (coalesced float4 loads)
    const float4* __restrict__ tgt = g_target4 + (long long)b * MM + mbase;
    for (int t = threadIdx.x; t < mcount; t += TPB) {
        tile[t] = tgt[t];
    }
    __syncthreads();

    // Load this thread's points into registers
    float ax[PPT], ay[PPT], az[PPT], x2[PPT], mn[PPT];
#pragma unroll
    for (int p = 0; p < PPT; p++) {
        float4 v = g_pred4[pbase + threadIdx.x + p * TPB];
        ax[p] = v.x; ay[p] = v.y; az[p] = v.z; x2[p] = v.w;
        mn[p] = __int_as_float(0x7F800000);
    }

    // Inner loop: per (point, target) = 3 FFMA + 1 FMNMX
    for (int t = 0; t < mcount; t++) {
        float4 tv = tile[t];  // broadcast read — conflict-free
#pragma unroll
        for (int p = 0; p < PPT; p++) {
            float v = fmaf(ax[p], tv.x,
                      fmaf(ay[p], tv.y,
                      fmaf(az[p], tv.z, tv.w)));
            mn[p] = fminf(mn[p], v);
        }
    }

    // Merge: d^2 = max(x2 + min(y2 - 2xy), 0) >= 0, so int atomicMin is exact
#pragma unroll
    for (int p = 0; p < PPT; p++) {
        int gi = pbase + threadIdx.x + p * TPB;
        float d2 = fmaxf(mn[p] + x2[p], 0.0f);
        atomicMin(&g_minbuf[gi], __float_as_int(d2));
    }
}

__global__ void reduce_kernel(float* __restrict__ out) {
    __shared__ float sh[256];
    float sum = 0.0f;
    for (int i = threadIdx.x; i < BB * SS; i += 256) {
        float d2 = __int_as_float(g_minbuf[i]);
        sum += sqrtf(d2);
    }
    sh[threadIdx.x] = sum;
    __syncthreads();
    for (int s = 128; s > 0; s >>= 1) {
        if (threadIdx.x < s) sh[threadIdx.x] += sh[threadIdx.x + s];
        __syncthreads();
    }
    if (threadIdx.x == 0) out[0] = sh[0] / (float)(BB * SS);
}

extern "C" void kernel_launch(void* const* d_in, const int* in_sizes, int n_in,
                              void* d_out, int out_size) {
    const float* pred = (const float*)d_in[0];
    const float* target = (const float*)d_in[1];
    const int* idx = (const int*)d_in[2];
    float* out = (float*)d_out;

    prep_target_kernel<<<(BB * MM + 255) / 256, 256>>>(target);
    prep_pred_kernel<<<(BB * SS + 255) / 256, 256>>>(pred, idx);

    dim3 grid(SBLOCKS, MCHUNKS);
    chamfer_main_kernel<<<grid, TPB>>>();

    reduce_kernel<<<1, 256>>>(out);
}

// round 4
// speedup vs baseline: 1.3180x; 1.3180x over previous
#include <cuda_runtime.h>
#include <cuda_bf16.h>

// Problem constants (fixed by the reference setup_inputs)
#define BB 2
#define NN 8192
#define MM 32768
#define SS 4096

#define TPB 128          // threads per block (main kernel)
#define PPT 8            // points per thread
#define PPB (TPB * PPT)  // 1024 points per block
#define SBLOCKS ((BB * SS) / PPB)  // 8
#define MCHUNKS 37
#define CHUNK 896        // 37 * 896 = 33152 >= 32768; all chunk sizes even
#define CHUNK2 (CHUNK / 2)

#define RBLOCKS 64       // reduction stage-1 blocks

// Device scratch (no allocations allowed)
__device__ float4 g_target4[BB * MM];   // (tx, ty, tz, |t|^2)
__device__ float4 g_pred4[BB * SS];     // (-2px, -2py, -2pz, |p|^2)
__device__ int    g_minbuf[BB * SS];    // min d^2 as int bits (nonneg floats order as ints)
__device__ float  g_partial[RBLOCKS];   // reduction partials

// ---- f32x2 packed helpers (Blackwell sm_103a) ----
__device__ __forceinline__ unsigned long long pk2(float lo, float hi) {
    unsigned long long r;
    asm("mov.b64 %0, {%1, %2};" : "=l"(r) : "f"(lo), "f"(hi));
    return r;
}
__device__ __forceinline__ void upk2(float& lo, float& hi, unsigned long long v) {
    asm("mov.b64 {%0, %1}, %2;" : "=f"(lo), "=f"(hi) : "l"(v));
}
__device__ __forceinline__ unsigned long long fma2(unsigned long long a,
                                                   unsigned long long b,
                                                   unsigned long long c) {
    unsigned long long d;
    asm("fma.rn.f32x2 %0, %1, %2, %3;" : "=l"(d) : "l"(a), "l"(b), "l"(c));
    return d;
}

__global__ void prep_target_kernel(const float* __restrict__ target) {
    int i = blockIdx.x * blockDim.x + threadIdx.x;
    if (i < BB * MM) {
        float x = target[3 * i + 0];
        float y = target[3 * i + 1];
        float z = target[3 * i + 2];
        g_target4[i] = make_float4(x, y, z, x * x + y * y + z * z);
    }
}

// idx is int32 on device (JAX default x64-disabled coerces int64 -> int32).
__global__ void prep_pred_kernel(const float* __restrict__ pred,
                                 const int* __restrict__ idx) {
    int i = blockIdx.x * blockDim.x + threadIdx.x;  // over B*S
    if (i < BB * SS) {
        int b = i / SS;
        int s = i % SS;
        int j = idx[s];
        j = min(max(j, 0), NN - 1);  // defensive clamp (no-op for valid input)
        const float* p = pred + ((long long)b * NN + j) * 3;
        float x = p[0], y = p[1], z = p[2];
        g_pred4[i] = make_float4(-2.0f * x, -2.0f * y, -2.0f * z,
                                 x * x + y * y + z * z);
        g_minbuf[i] = 0x7F800000;  // +inf
    }
}

__global__ void __launch_bounds__(TPB) chamfer_main_kernel() {
    // Target tile, packed two-targets-per-entry: (t[2k].c, t[2k+1].c)
    __shared__ unsigned long long tile_x[CHUNK2];
    __shared__ unsigned long long tile_y[CHUNK2];
    __shared__ unsigned long long tile_z[CHUNK2];
    __shared__ unsigned long long tile_w[CHUNK2];

    const int sblk = blockIdx.x;            // 0..SBLOCKS-1
    const int mblk = blockIdx.y;            // 0..MCHUNKS-1
    const int pbase = sblk * PPB;           // global point base in [0, B*S)
    const int b = pbase / SS;               // batch of this point block
    const int mbase = mblk * CHUNK;
    const int mcount = min(CHUNK, MM - mbase);   // 896 or 512: always even
    const int mcount2 = mcount >> 1;

    // Load + pack target chunk into shared memory
    const float4* __restrict__ tgt = g_target4 + (long long)b * MM + mbase;
    for (int t = threadIdx.x; t < mcount2; t += TPB) {
        float4 a = tgt[2 * t];
        float4 c = tgt[2 * t + 1];
        tile_x[t] = pk2(a.x, c.x);
        tile_y[t] = pk2(a.y, c.y);
        tile_z[t] = pk2(a.z, c.z);
        tile_w[t] = pk2(a.w, c.w);
    }
    __syncthreads();

    // Load this thread's points; duplicate coords into both f32x2 halves
    unsigned long long axx[PPT], ayy[PPT], azz[PPT];
    float x2[PPT], mn0[PPT], mn1[PPT];
#pragma unroll
    for (int p = 0; p < PPT; p++) {
        float4 v = g_pred4[pbase + threadIdx.x + p * TPB];
        axx[p] = pk2(v.x, v.x);
        ayy[p] = pk2(v.y, v.y);
        azz[p] = pk2(v.z, v.z);
        x2[p] = v.w;
        mn0[p] = __int_as_float(0x7F800000);
        mn1[p] = __int_as_float(0x7F800000);
    }

    // Inner loop: per 2 (point,target) pairs = 3 FFMA2 (fma pipe) + 2 FMNMX (alu pipe)
    for (int t = 0; t < mcount2; t++) {
        unsigned long long X = tile_x[t];
        unsigned long long Y = tile_y[t];
        unsigned long long Z = tile_z[t];
        unsigned long long W = tile_w[t];
#pragma unroll
        for (int p = 0; p < PPT; p++) {
            unsigned long long v = fma2(azz[p], Z, W);
            v = fma2(ayy[p], Y, v);
            v = fma2(axx[p], X, v);
            float v0, v1;
            upk2(v0, v1, v);
            mn0[p] = fminf(mn0[p], v0);
            mn1[p] = fminf(mn1[p], v1);
        }
    }

    // Merge: d^2 = max(x2 + min(y2 - 2xy), 0) >= 0, so int atomicMin is exact
#pragma unroll
    for (int p = 0; p < PPT; p++) {
        int gi = pbase + threadIdx.x + p * TPB;
        float d2 = fmaxf(fminf(mn0[p], mn1[p]) + x2[p], 0.0f);
        atomicMin(&g_minbuf[gi], __float_as_int(d2));
    }
}

// Stage 1: 64 blocks x 128 threads, one element each -> per-block partial (deterministic)
__global__ void __launch_bounds__(128) reduce1_kernel() {
    __shared__ float sh[4];
    int i = blockIdx.x * 128 + threadIdx.x;   // covers exactly B*S = 8192
    float s = sqrtf(__int_as_float(g_minbuf[i]));
#pragma unroll
    for (int o = 16; o > 0; o >>= 1)
        s += __shfl_down_sync(0xFFFFFFFFu, s, o);
    if ((threadIdx.x & 31) == 0) sh[threadIdx.x >> 5] = s;
    __syncthreads();
    if (threadIdx.x == 0)
        g_partial[blockIdx.x] = sh[0] + sh[1] + sh[2] + sh[3];
}

// Stage 2: single warp sums the 64 partials
__global__ void reduce2_kernel(float* __restrict__ out) {
    float s = g_partial[threadIdx.x] + g_partial[threadIdx.x + 32];
#pragma unroll
    for (int o = 16; o > 0; o >>= 1)
        s += __shfl_down_sync(0xFFFFFFFFu, s, o);
    if (threadIdx.x == 0) out[0] = s / (float)(BB * SS);
}

extern "C" void kernel_launch(void* const* d_in, const int* in_sizes, int n_in,
                              void* d_out, int out_size) {
    const float* pred = (const float*)d_in[0];
    const float* target = (const float*)d_in[1];
    const int* idx = (const int*)d_in[2];
    float* out = (float*)d_out;

    prep_target_kernel<<<(BB * MM + 255) / 256, 256>>>(target);
    prep_pred_kernel<<<(BB * SS + 255) / 256, 256>>>(pred, idx);

    dim3 grid(SBLOCKS, MCHUNKS);
    chamfer_main_kernel<<<grid, TPB>>>();

    reduce1_kernel<<<RBLOCKS, 128>>>();
    reduce2_kernel<<<1, 32>>>(out);
}